// round 4
// baseline (speedup 1.0000x reference)
#include <cuda_runtime.h>
#include <math.h>

#define NIMG 16
#define NCLS 80
#define NREF 256
#define CAP  8192
#define THW  20267
#define THWPAD 20480
#define NSEG 6480       // segments per image (class-aligned 256-chunks)
#define NSEGPAD 6528

// ---------------- scratch (device globals; no allocs) ----------------
__device__ float g_ctrD[NIMG * THWPAD];             // (1 + e^{-ctr}) surrogate denom
__device__ float g_segD[NIMG * NSEGPAD];            // per-segment min D
__device__ int   g_bcut[NIMG];
__device__ int   g_cnt[NIMG];
__device__ unsigned long long g_cand[NIMG][CAP];

struct P5 { const float* lg[5]; const float* rg[5]; const float* ct[5]; const float* lc[5]; };

__constant__ int c_HW[5]   = {15200, 3800, 950, 247, 70};
__constant__ int c_hwb[5]  = {0, 15200, 19000, 19950, 20197};
__constant__ int c_rb[5]   = {0, 1216000, 1520000, 1596000, 1615760};
__constant__ int c_spc[5]  = {60, 15, 4, 1, 1};            // seg chunks per class
__constant__ int c_segb[5] = {0, 4800, 6000, 6320, 6400};  // seg base per level
__constant__ float c_str[5] = {8.f, 16.f, 32.f, 64.f, 128.f};

// e^{-x}: exp2 via floor + cubic minimax on [0,1). rel err ~2e-4, MUFU-free.
// Used ONLY as a monotone-consistent surrogate (same fn in minred & compact).
__device__ __forceinline__ float expneg(float x) {
    float u = fminf(fmaxf(-1.44269504f * x, -40.f), 40.f);
    float nf = floorf(u);
    float f = u - nf;
    float p = fmaf(fmaf(fmaf(0.079471f, f, 0.224696f), f, 0.695833f), f, 1.0f);
    return p * __int_as_float(((int)nf + 127) << 23);
}

// Reference-exact sigmoid: XLA logistic_expander exp form, f32 exp -> libdevice
// __nv_expf (== CUDA expf without fast-math), IEEE rn add/div. Survivors only.
__device__ __forceinline__ float sig_ref(float x) {
    return 1.0f / (1.0f + expf(-x));
}

__device__ __forceinline__ void seg_decode(int wid, int& l, int& c, int& hw0, int& HW) {
    if (wid < 4800) l = 0; else if (wid < 6000) l = 1; else if (wid < 6320) l = 2;
    else if (wid < 6400) l = 3; else l = 4;
    int s = wid - c_segb[l];
    int spc = c_spc[l];
    c = s / spc;
    hw0 = (s - c * spc) * 256;
    HW = c_HW[l];
}

__global__ void k_ctr(P5 p) {
    int i = blockIdx.x * blockDim.x + threadIdx.x;
    if (i < NIMG) g_cnt[i] = 0;
    if (i >= NIMG * THW) return;
    int n = i / THW, g = i - n * THW;
    int l, hw;
    if (g < 15200)      { l = 0; hw = g; }
    else if (g < 19000) { l = 1; hw = g - 15200; }
    else if (g < 19950) { l = 2; hw = g - 19000; }
    else if (g < 20197) { l = 3; hw = g - 19950; }
    else                { l = 4; hw = g - 20197; }
    g_ctrD[n * THWPAD + g] = 1.0f + expneg(p.ct[l][n * c_HW[l] + hw]);
}

__global__ void k_minred(P5 p) {
    int n = blockIdx.y;
    int wid = blockIdx.x * 8 + (threadIdx.x >> 5);
    int lane = threadIdx.x & 31;
    if (wid >= NSEG) return;
    int l, c, hw0, HW;
    seg_decode(wid, l, c, hw0, HW);
    const float* lg = p.lg[l] + ((size_t)n * NCLS + c) * HW;
    const float* cd = g_ctrD + n * THWPAD + c_hwb[l];
    float m = 3.4e38f;
    #pragma unroll
    for (int i = 0; i < 8; i++) {
        int hw = hw0 + lane + i * 32;
        if (hw < HW) {
            float a = lg[hw];
            if (a > -2.95f) {
                float D = (1.0f + expneg(a)) * cd[hw];
                m = fminf(m, D);
            }
        }
    }
    #pragma unroll
    for (int o = 16; o; o >>= 1) m = fminf(m, __shfl_xor_sync(0xffffffffu, m, o));
    if (lane == 0) g_segD[n * NSEGPAD + wid] = m;
}

__global__ void k_cut() {
    __shared__ int hist[4096];
    __shared__ int bres;
    int n = blockIdx.x, tid = threadIdx.x;
    for (int i = tid; i < 4096; i += blockDim.x) hist[i] = 0;
    if (tid == 0) bres = 4095;
    __syncthreads();
    for (int i = tid; i < NSEG; i += blockDim.x) {
        unsigned b = __float_as_uint(g_segD[n * NSEGPAD + i]) >> 19;
        atomicAdd(&hist[min(b, 4095u)], 1);
    }
    __syncthreads();
    if (tid < 32) {
        int cum = 0;
        for (int s0 = 0; s0 < 4096; s0 += 32) {
            int v = hist[s0 + tid];
            int sc = v;
            #pragma unroll
            for (int o = 1; o < 32; o <<= 1) {
                int t = __shfl_up_sync(0xffffffffu, sc, o);
                if (tid >= o) sc += t;
            }
            int tot = __shfl_sync(0xffffffffu, sc, 31);
            unsigned bal = __ballot_sync(0xffffffffu, cum + sc >= NREF);
            if (bal) { if (tid == 0) bres = s0 + __ffs(bal) - 1; break; }
            cum += tot;
        }
    }
    __syncthreads();
    if (tid == 0) g_bcut[n] = min(bres + 1, 4095);   // +1 bucket slop (safety)
}

__global__ void k_compact(P5 p) {
    int n = blockIdx.y;
    int wid = blockIdx.x * 8 + (threadIdx.x >> 5);
    int lane = threadIdx.x & 31;
    if (wid >= NSEG) return;
    int bcut = g_bcut[n];
    int l, c, hw0, HW;
    seg_decode(wid, l, c, hw0, HW);
    const float* lg = p.lg[l] + ((size_t)n * NCLS + c) * HW;
    const float* cd = g_ctrD + n * THWPAD + c_hwb[l];
    const float* ctp = p.ct[l] + (size_t)n * HW;
    #pragma unroll
    for (int i = 0; i < 8; i++) {
        int hw = hw0 + lane + i * 32;
        if (hw < HW) {
            float a = lg[hw];
            if (a > -2.95f) {
                float D = (1.0f + expneg(a)) * cd[hw];
                if ((int)(__float_as_uint(D) >> 19) <= bcut) {
                    float sa = sig_ref(a);
                    if (sa > 0.05f) {                       // exact reference gate
                        float v = sa * sig_ref(ctp[hw]);
                        if (v > 0.0f) {
                            unsigned rank = (unsigned)(c_rb[l] + hw * NCLS + c);
                            unsigned long long kk =
                                ((unsigned long long)__float_as_uint(v) << 32) |
                                (0x7FFFFFFFu - rank);
                            int pos = atomicAdd(&g_cnt[n], 1);
                            if (pos < CAP) g_cand[n][pos] = kk;
                        }
                    }
                }
            }
        }
    }
}

__global__ void __launch_bounds__(512) k_sort(P5 p, float* out) {
    __shared__ union { int hist[8192]; unsigned long long buf[2048]; } u;  // 32KB
    __shared__ int m, bs;
    int n = blockIdx.x, tid = threadIdx.x, nt = blockDim.x;
    int cnt = min(g_cnt[n], CAP);
    for (int i = tid; i < 8192; i += nt) u.hist[i] = 0;
    if (tid == 0) { m = 0; bs = 0; }
    __syncthreads();

    for (int i = tid; i < cnt; i += nt)
        atomicAdd(&u.hist[(int)(g_cand[n][i] >> 51)], 1);
    __syncthreads();

    if (tid < 32) {
        int cum = 0;
        for (int s0 = 8192 - 32; s0 >= 0; s0 -= 32) {
            int v = u.hist[s0 + tid];
            int sc = v;                                  // inclusive suffix sum
            #pragma unroll
            for (int o = 1; o < 32; o <<= 1) {
                int t = __shfl_down_sync(0xffffffffu, sc, o);
                if (tid + o < 32) sc += t;
            }
            unsigned bal = __ballot_sync(0xffffffffu, cum + sc >= NREF);
            if (bal) {
                int hi = 31 - __clz(bal);                // largest bucket with cum>=256
                if (tid == hi) bs = s0 + hi;
                break;
            }
            cum += __shfl_sync(0xffffffffu, sc, 0);
        }
    }
    __syncthreads();
    int bcut2 = bs;
    __syncthreads();                                     // hist dead; buf overlay safe

    for (int i = tid; i < cnt; i += nt) {
        unsigned long long kk = g_cand[n][i];
        if ((int)(kk >> 51) >= bcut2) {
            int pos = atomicAdd(&m, 1);
            if (pos < 2048) u.buf[pos] = kk;
        }
    }
    __syncthreads();
    int mm = min(m, 2048);
    for (int i = tid; i < 2048; i += nt) if (i >= mm) u.buf[i] = 0ULL;
    __syncthreads();

    // bitonic sort descending; keys unique (rank embedded) -> deterministic order
    for (int k = 2; k <= 2048; k <<= 1) {
        for (int j = k >> 1; j > 0; j >>= 1) {
            for (int i = tid; i < 2048; i += nt) {
                int ixj = i ^ j;
                if (ixj > i) {
                    unsigned long long x = u.buf[i], y = u.buf[ixj];
                    bool desc = ((i & k) == 0);
                    if (desc ? (x < y) : (x > y)) { u.buf[i] = y; u.buf[ixj] = x; }
                }
            }
            __syncthreads();
        }
    }

    if (tid < NREF) {
        unsigned long long kk = u.buf[tid];
        float sc = 0.f, x0 = 0.f, y0 = 0.f, x1 = 0.f, y1 = 0.f;
        int cls = 0, lvl = 0;
        if (kk) {
            float v = __uint_as_float((unsigned)(kk >> 32));
            unsigned rank = 0x7FFFFFFFu - (unsigned)(kk & 0xFFFFFFFFu);
            int l;
            if (rank < 1216000u) l = 0;
            else if (rank < 1520000u) l = 1;
            else if (rank < 1596000u) l = 2;
            else if (rank < 1615760u) l = 3;
            else l = 4;
            int HWl = c_HW[l];
            int r = (int)rank - c_rb[l];
            int loc = r / NCLS;
            cls = r - NCLS * loc;
            lvl = l;
            float strf = c_str[l];
            float px = p.lc[l][2 * loc], py = p.lc[l][2 * loc + 1];
            const float* rg = p.rg[l] + (size_t)n * 4 * HWl;
            float r0 = rg[loc] * strf;
            float r1 = rg[HWl + loc] * strf;
            float r2 = rg[2 * HWl + loc] * strf;
            float r3 = rg[3 * HWl + loc] * strf;
            sc = sqrtf(v);
            x0 = px - r0; y0 = py - r1; x1 = px + r2; y1 = py + r3;
        }
        int o = n * NREF + tid;
        out[o] = sc;
        float* ob = out + NIMG * NREF;
        ob[o * 4 + 0] = x0; ob[o * 4 + 1] = y0;
        ob[o * 4 + 2] = x1; ob[o * 4 + 3] = y1;
        float* oc = out + NIMG * NREF * 5;
        oc[o] = (float)cls;
        float* ol = out + NIMG * NREF * 6;
        ol[o] = (float)lvl;
    }
}

extern "C" void kernel_launch(void* const* d_in, const int* in_sizes, int n_in,
                              void* d_out, int out_size) {
    P5 p;
    for (int l = 0; l < 5; l++) {
        p.lg[l] = (const float*)d_in[4 * l + 0];
        p.rg[l] = (const float*)d_in[4 * l + 1];
        p.ct[l] = (const float*)d_in[4 * l + 2];
        p.lc[l] = (const float*)d_in[4 * l + 3];
    }
    k_ctr<<<(NIMG * THW + 255) / 256, 256>>>(p);
    dim3 g(810, NIMG);       // 810*8 warps >= 6480 segments
    k_minred<<<g, 256>>>(p);
    k_cut<<<NIMG, 256>>>();
    k_compact<<<g, 256>>>(p);
    k_sort<<<NIMG, 512>>>(p, (float*)d_out);
}

// round 5
// speedup vs baseline: 1.6646x; 1.6646x over previous
#include <cuda_runtime.h>
#include <math.h>

#define NIMG 16
#define NCLS 80
#define NREF 256
#define CAP  8192
#define LCAP 8192
#define THWPAD 20480
#define NSEG 6480       // segments per image (class-aligned 256-chunks)
#define NSEGPAD 6528

// ---------------- scratch (device globals; no allocs) ----------------
__device__ float g_ctrD[NIMG * THWPAD];             // (1 + e^{-ctr}), padded layout
__device__ float g_segD[NIMG * NSEGPAD];            // per-segment min D
__device__ int   g_bcut[NIMG];
__device__ int   g_cnt[NIMG];
__device__ int   g_lcnt[NIMG];
__device__ int   g_seglist[NIMG][LCAP];
__device__ unsigned long long g_cand[NIMG][CAP];

struct P5 { const float* lg[5]; const float* rg[5]; const float* ct[5]; const float* lc[5]; };

__constant__ int c_HW[5]   = {15200, 3800, 950, 247, 70};
__constant__ int c_hwb2[5] = {0, 15232, 19072, 20032, 20288};  // 16B-aligned bases
__constant__ int c_rb[5]   = {0, 1216000, 1520000, 1596000, 1615760};
__constant__ float c_str[5] = {8.f, 16.f, 32.f, 64.f, 128.f};

// e^{-x} surrogate: exp2 via floor + cubic minimax, rel err ~2e-4, MUFU-free.
// MUST be the identical computation in k_ctr / k_minred / k_compact.
__device__ __forceinline__ float expneg(float x) {
    float u = fminf(fmaxf(-1.44269504f * x, -126.f), 126.f);
    float nf = floorf(u);
    float f = u - nf;
    float pm = fmaf(fmaf(fmaf(0.079471f, f, 0.224696f), f, 0.695833f), f, 1.0f);
    return pm * __int_as_float(((int)nf + 127) << 23);
}

// surrogate inverse-score key; gated elements -> +inf (never win a min)
__device__ __forceinline__ float Dkey(float a, float cd) {
    float D = fmaf(expneg(a), 1.0f, 1.0f) * cd;   // (1 + e^-a) * (1 + e^-c)
    return (a > -2.95f) ? D : 3.4e38f;
}

// Reference-exact sigmoid (libdevice expf == XLA f32 exp), survivors only.
__device__ __forceinline__ float sig_ref(float x) {
    return 1.0f / (1.0f + expf(-x));
}

struct Seg { int l, c, hw0, HW; };
__device__ __forceinline__ Seg seg_decode(int wid) {
    Seg s;
    if (wid < 4800)      { s.l=0; s.c=wid/60;  s.hw0=(wid-s.c*60)<<8;  s.HW=15200; }
    else if (wid < 6000) { int t=wid-4800; s.l=1; s.c=t/15; s.hw0=(t-s.c*15)<<8; s.HW=3800; }
    else if (wid < 6320) { int t=wid-6000; s.l=2; s.c=t>>2; s.hw0=(t&3)<<8; s.HW=950; }
    else if (wid < 6400) { s.l=3; s.c=wid-6320; s.hw0=0; s.HW=247; }
    else                 { s.l=4; s.c=wid-6400; s.hw0=0; s.HW=70; }
    return s;
}

__global__ void k_ctr(P5 p) {
    int i = blockIdx.x * blockDim.x + threadIdx.x;
    if (i < NIMG) { g_cnt[i] = 0; g_lcnt[i] = 0; }
    if (i >= NIMG * THWPAD) return;
    int n = i / THWPAD, g = i - n * THWPAD;
    int l, hw;
    if (g < 15200)                     { l = 0; hw = g; }
    else if (g >= 15232 && g < 19032)  { l = 1; hw = g - 15232; }
    else if (g >= 19072 && g < 20022)  { l = 2; hw = g - 19072; }
    else if (g >= 20032 && g < 20279)  { l = 3; hw = g - 20032; }
    else if (g >= 20288 && g < 20358)  { l = 4; hw = g - 20288; }
    else return;
    g_ctrD[i] = 1.0f + expneg(p.ct[l][n * c_HW[l] + hw]);
}

__global__ void k_minred(P5 p) {
    int n = blockIdx.y;
    int wid = blockIdx.x * 8 + (threadIdx.x >> 5);
    int lane = threadIdx.x & 31;
    if (wid >= NSEG) return;
    Seg sg = seg_decode(wid);
    const float* lg = p.lg[sg.l] + ((size_t)n * NCLS + sg.c) * sg.HW;
    const float* cd = g_ctrD + n * THWPAD + c_hwb2[sg.l];
    float m = 3.4e38f;
    if (sg.l < 2) {
        int h0 = sg.hw0 + lane * 4;
        int h1 = h0 + 128;
        bool v0 = (h0 + 4 <= sg.HW), v1 = (h1 + 4 <= sg.HW);
        float4 a0, d0, a1, d1;
        if (v0) { a0 = *(const float4*)(lg + h0); d0 = *(const float4*)(cd + h0); }
        if (v1) { a1 = *(const float4*)(lg + h1); d1 = *(const float4*)(cd + h1); }
        if (v0) {
            m = fminf(m, Dkey(a0.x, d0.x)); m = fminf(m, Dkey(a0.y, d0.y));
            m = fminf(m, Dkey(a0.z, d0.z)); m = fminf(m, Dkey(a0.w, d0.w));
        }
        if (v1) {
            m = fminf(m, Dkey(a1.x, d1.x)); m = fminf(m, Dkey(a1.y, d1.y));
            m = fminf(m, Dkey(a1.z, d1.z)); m = fminf(m, Dkey(a1.w, d1.w));
        }
    } else {
        #pragma unroll
        for (int i = 0; i < 8; i++) {
            int h = sg.hw0 + lane + i * 32;
            if (h < sg.HW) m = fminf(m, Dkey(lg[h], cd[h]));
        }
    }
    #pragma unroll
    for (int o = 16; o; o >>= 1) m = fminf(m, __shfl_xor_sync(0xffffffffu, m, o));
    if (lane == 0) g_segD[n * NSEGPAD + wid] = m;
}

__global__ void k_cut() {
    __shared__ int hist[4096];
    __shared__ int bres;
    int n = blockIdx.x, tid = threadIdx.x, nt = blockDim.x;
    for (int i = tid; i < 4096; i += nt) hist[i] = 0;
    if (tid == 0) bres = 4095;
    __syncthreads();
    for (int i = tid; i < NSEG; i += nt) {
        unsigned b = __float_as_uint(g_segD[n * NSEGPAD + i]) >> 19;
        atomicAdd(&hist[min(b, 4095u)], 1);
    }
    __syncthreads();
    if (tid < 32) {
        int cum = 0;
        for (int s0 = 0; s0 < 4096; s0 += 32) {
            int v = hist[s0 + tid];
            int sc = v;
            #pragma unroll
            for (int o = 1; o < 32; o <<= 1) {
                int t = __shfl_up_sync(0xffffffffu, sc, o);
                if (tid >= o) sc += t;
            }
            int tot = __shfl_sync(0xffffffffu, sc, 31);
            unsigned bal = __ballot_sync(0xffffffffu, cum + sc >= NREF);
            if (bal) { if (tid == 0) bres = s0 + __ffs(bal) - 1; break; }
            cum += tot;
        }
    }
    __syncthreads();
    int bc = min(bres + 1, 4095);       // +1 bucket: surrogate-vs-exact slop
    if (tid == 0) g_bcut[n] = bc;
    // build qualifying-segment list (order irrelevant)
    for (int i = tid; i < NSEG; i += nt) {
        unsigned b = __float_as_uint(g_segD[n * NSEGPAD + i]) >> 19;
        if ((int)b <= bc) {
            int pos = atomicAdd(&g_lcnt[n], 1);
            if (pos < LCAP) g_seglist[n][pos] = i;
        }
    }
}

__global__ void k_compact(P5 p) {
    int n = blockIdx.y;
    int warp = blockIdx.x * 8 + (threadIdx.x >> 5);
    int lane = threadIdx.x & 31;
    int nwarp = gridDim.x * 8;
    int bcut = g_bcut[n];
    int lcnt = min(g_lcnt[n], LCAP);
    for (int j = warp; j < lcnt; j += nwarp) {
        Seg sg = seg_decode(g_seglist[n][j]);
        const float* lg = p.lg[sg.l] + ((size_t)n * NCLS + sg.c) * sg.HW;
        const float* cd = g_ctrD + n * THWPAD + c_hwb2[sg.l];
        const float* ctp = p.ct[sg.l] + (size_t)n * sg.HW;
        #pragma unroll
        for (int i = 0; i < 8; i++) {
            int hw = sg.hw0 + lane + i * 32;
            if (hw < sg.HW) {
                float a = lg[hw];
                float D = Dkey(a, cd[hw]);
                if ((int)(__float_as_uint(D) >> 19) <= bcut) {
                    float sa = sig_ref(a);
                    if (sa > 0.05f) {                       // exact reference gate
                        float v = sa * sig_ref(ctp[hw]);
                        if (v > 0.0f) {
                            unsigned rank = (unsigned)(c_rb[sg.l] + hw * NCLS + sg.c);
                            unsigned long long kk =
                                ((unsigned long long)__float_as_uint(v) << 32) |
                                (0x7FFFFFFFu - rank);
                            int pos = atomicAdd(&g_cnt[n], 1);
                            if (pos < CAP) g_cand[n][pos] = kk;
                        }
                    }
                }
            }
        }
    }
}

__global__ void __launch_bounds__(512) k_sort(P5 p, float* out) {
    __shared__ union { int hist[8192]; unsigned long long buf[2048]; } u;  // 32KB
    __shared__ int m, bs;
    int n = blockIdx.x, tid = threadIdx.x, nt = blockDim.x;
    int cnt = min(g_cnt[n], CAP);
    for (int i = tid; i < 8192; i += nt) u.hist[i] = 0;
    if (tid == 0) { m = 0; bs = 0; }
    __syncthreads();

    for (int i = tid; i < cnt; i += nt)
        atomicAdd(&u.hist[(int)(g_cand[n][i] >> 51)], 1);
    __syncthreads();

    if (tid < 32) {
        int cum = 0;
        for (int s0 = 8192 - 32; s0 >= 0; s0 -= 32) {
            int v = u.hist[s0 + tid];
            int sc = v;                                  // inclusive suffix sum
            #pragma unroll
            for (int o = 1; o < 32; o <<= 1) {
                int t = __shfl_down_sync(0xffffffffu, sc, o);
                if (tid + o < 32) sc += t;
            }
            unsigned bal = __ballot_sync(0xffffffffu, cum + sc >= NREF);
            if (bal) {
                int hi = 31 - __clz(bal);                // largest bucket with cum>=256
                if (tid == hi) bs = s0 + hi;
                break;
            }
            cum += __shfl_sync(0xffffffffu, sc, 0);
        }
    }
    __syncthreads();
    int bcut2 = bs;
    __syncthreads();                                     // hist dead; buf overlay safe

    for (int i = tid; i < cnt; i += nt) {
        unsigned long long kk = g_cand[n][i];
        if ((int)(kk >> 51) >= bcut2) {
            int pos = atomicAdd(&m, 1);
            if (pos < 2048) u.buf[pos] = kk;
        }
    }
    __syncthreads();
    int mm = min(m, 2048);
    for (int i = tid; i < 2048; i += nt) if (i >= mm) u.buf[i] = 0ULL;
    __syncthreads();

    // bitonic sort descending; keys unique (rank embedded) -> deterministic
    for (int k = 2; k <= 2048; k <<= 1) {
        for (int j = k >> 1; j > 0; j >>= 1) {
            for (int i = tid; i < 2048; i += nt) {
                int ixj = i ^ j;
                if (ixj > i) {
                    unsigned long long x = u.buf[i], y = u.buf[ixj];
                    bool desc = ((i & k) == 0);
                    if (desc ? (x < y) : (x > y)) { u.buf[i] = y; u.buf[ixj] = x; }
                }
            }
            __syncthreads();
        }
    }

    if (tid < NREF) {
        unsigned long long kk = u.buf[tid];
        float sc = 0.f, x0 = 0.f, y0 = 0.f, x1 = 0.f, y1 = 0.f;
        int cls = 0, lvl = 0;
        if (kk) {
            float v = __uint_as_float((unsigned)(kk >> 32));
            unsigned rank = 0x7FFFFFFFu - (unsigned)(kk & 0xFFFFFFFFu);
            int l;
            if (rank < 1216000u) l = 0;
            else if (rank < 1520000u) l = 1;
            else if (rank < 1596000u) l = 2;
            else if (rank < 1615760u) l = 3;
            else l = 4;
            int HWl = c_HW[l];
            int r = (int)rank - c_rb[l];
            int loc = r / NCLS;
            cls = r - NCLS * loc;
            lvl = l;
            float strf = c_str[l];
            float px = p.lc[l][2 * loc], py = p.lc[l][2 * loc + 1];
            const float* rg = p.rg[l] + (size_t)n * 4 * HWl;
            float r0 = rg[loc] * strf;
            float r1 = rg[HWl + loc] * strf;
            float r2 = rg[2 * HWl + loc] * strf;
            float r3 = rg[3 * HWl + loc] * strf;
            sc = sqrtf(v);
            x0 = px - r0; y0 = py - r1; x1 = px + r2; y1 = py + r3;
        }
        int o = n * NREF + tid;
        out[o] = sc;
        float* ob = out + NIMG * NREF;
        ob[o * 4 + 0] = x0; ob[o * 4 + 1] = y0;
        ob[o * 4 + 2] = x1; ob[o * 4 + 3] = y1;
        float* oc = out + NIMG * NREF * 5;
        oc[o] = (float)cls;
        float* ol = out + NIMG * NREF * 6;
        ol[o] = (float)lvl;
    }
}

extern "C" void kernel_launch(void* const* d_in, const int* in_sizes, int n_in,
                              void* d_out, int out_size) {
    P5 p;
    for (int l = 0; l < 5; l++) {
        p.lg[l] = (const float*)d_in[4 * l + 0];
        p.rg[l] = (const float*)d_in[4 * l + 1];
        p.ct[l] = (const float*)d_in[4 * l + 2];
        p.lc[l] = (const float*)d_in[4 * l + 3];
    }
    k_ctr<<<(NIMG * THWPAD + 255) / 256, 256>>>(p);
    dim3 g(810, NIMG);       // 810*8 warps >= 6480 segments
    k_minred<<<g, 256>>>(p);
    k_cut<<<NIMG, 256>>>();
    dim3 gc(64, NIMG);       // 512 warps/image grid-stride over seglist
    k_compact<<<gc, 256>>>(p);
    k_sort<<<NIMG, 512>>>(p, (float*)d_out);
}

// round 6
// speedup vs baseline: 2.5265x; 1.5178x over previous
#include <cuda_runtime.h>
#include <math.h>

#define NIMG 16
#define NCLS 80
#define NREF 256
#define CAP  8192
#define LCAP 8192
#define THWPAD 20480
#define NSEG 6480       // segments per image (class-aligned 256-chunks)
#define NSEGPAD 6528

// ---------------- scratch (device globals; no allocs) ----------------
__device__ float g_ctrD[NIMG * THWPAD];             // (1 + e^{-ctr}), padded layout
__device__ float g_segD[NIMG * NSEGPAD];            // per-segment min D
__device__ int   g_bcut[NIMG];
__device__ int   g_cnt[NIMG];
__device__ int   g_lcnt[NIMG];
__device__ int   g_seglist[NIMG][LCAP];
__device__ unsigned long long g_cand[NIMG][CAP];

struct P5 { const float* lg[5]; const float* rg[5]; const float* ct[5]; const float* lc[5]; };

__constant__ int c_HW[5]   = {15200, 3800, 950, 247, 70};
__constant__ int c_hwb2[5] = {0, 15232, 19072, 20032, 20288};  // 16B-aligned bases
__constant__ int c_rb[5]   = {0, 1216000, 1520000, 1596000, 1615760};
__constant__ float c_str[5] = {8.f, 16.f, 32.f, 64.f, 128.f};

// e^{-x} surrogate: exp2 via floor + cubic minimax, rel err ~2e-4, MUFU-free.
// MUST be the identical computation in k_ctr / k_minred / k_compact.
__device__ __forceinline__ float expneg(float x) {
    float u = fminf(fmaxf(-1.44269504f * x, -126.f), 126.f);
    float nf = floorf(u);
    float f = u - nf;
    float pm = fmaf(fmaf(fmaf(0.079471f, f, 0.224696f), f, 0.695833f), f, 1.0f);
    return pm * __int_as_float(((int)nf + 127) << 23);
}

// surrogate inverse-score key; gated elements -> +inf (never win a min)
__device__ __forceinline__ float Dkey(float a, float cd) {
    float D = fmaf(expneg(a), cd, cd);            // (1 + e^-a) * cd
    return (a > -2.95f) ? D : 3.4e38f;
}

// Reference-exact sigmoid (libdevice expf == XLA f32 exp), survivors only.
__device__ __forceinline__ float sig_ref(float x) {
    return 1.0f / (1.0f + expf(-x));
}

struct Seg { int l, c, hw0, HW; };
__device__ __forceinline__ Seg seg_decode(int wid) {
    Seg s;
    if (wid < 4800)      { s.l=0; s.c=wid/60;  s.hw0=(wid-s.c*60)<<8;  s.HW=15200; }
    else if (wid < 6000) { int t=wid-4800; s.l=1; s.c=t/15; s.hw0=(t-s.c*15)<<8; s.HW=3800; }
    else if (wid < 6320) { int t=wid-6000; s.l=2; s.c=t>>2; s.hw0=(t&3)<<8; s.HW=950; }
    else if (wid < 6400) { s.l=3; s.c=wid-6320; s.hw0=0; s.HW=247; }
    else                 { s.l=4; s.c=wid-6400; s.hw0=0; s.HW=70; }
    return s;
}

__global__ void k_ctr(P5 p) {
    int i = blockIdx.x * blockDim.x + threadIdx.x;
    if (i < NIMG) { g_cnt[i] = 0; g_lcnt[i] = 0; }
    if (i >= NIMG * THWPAD) return;
    int n = i / THWPAD, g = i - n * THWPAD;
    int l, hw;
    if (g < 15200)                     { l = 0; hw = g; }
    else if (g >= 15232 && g < 19032)  { l = 1; hw = g - 15232; }
    else if (g >= 19072 && g < 20022)  { l = 2; hw = g - 19072; }
    else if (g >= 20032 && g < 20279)  { l = 3; hw = g - 20032; }
    else if (g >= 20288 && g < 20358)  { l = 4; hw = g - 20288; }
    else return;
    g_ctrD[i] = 1.0f + expneg(p.ct[l][n * c_HW[l] + hw]);
}

__global__ void k_minred(P5 p) {
    int n = blockIdx.y;
    int wid = blockIdx.x * 8 + (threadIdx.x >> 5);
    int lane = threadIdx.x & 31;
    if (wid >= NSEG) return;
    Seg sg = seg_decode(wid);
    const float* lg = p.lg[sg.l] + ((size_t)n * NCLS + sg.c) * sg.HW;
    const float* cd = g_ctrD + n * THWPAD + c_hwb2[sg.l];
    float m = 3.4e38f;
    if (sg.l < 2) {
        int h0 = sg.hw0 + lane * 4;
        int h1 = h0 + 128;
        bool v0 = (h0 + 4 <= sg.HW), v1 = (h1 + 4 <= sg.HW);
        float4 a0, d0, a1, d1;
        if (v0) { a0 = *(const float4*)(lg + h0); d0 = *(const float4*)(cd + h0); }
        if (v1) { a1 = *(const float4*)(lg + h1); d1 = *(const float4*)(cd + h1); }
        if (v0) {
            m = fminf(m, Dkey(a0.x, d0.x)); m = fminf(m, Dkey(a0.y, d0.y));
            m = fminf(m, Dkey(a0.z, d0.z)); m = fminf(m, Dkey(a0.w, d0.w));
        }
        if (v1) {
            m = fminf(m, Dkey(a1.x, d1.x)); m = fminf(m, Dkey(a1.y, d1.y));
            m = fminf(m, Dkey(a1.z, d1.z)); m = fminf(m, Dkey(a1.w, d1.w));
        }
    } else {
        #pragma unroll
        for (int i = 0; i < 8; i++) {
            int h = sg.hw0 + lane + i * 32;
            if (h < sg.HW) m = fminf(m, Dkey(lg[h], cd[h]));
        }
    }
    #pragma unroll
    for (int o = 16; o; o >>= 1) m = fminf(m, __shfl_xor_sync(0xffffffffu, m, o));
    if (lane == 0) g_segD[n * NSEGPAD + wid] = m;
}

// hierarchical ascending rank-select over 4096 buckets, then build seglist
__global__ void __launch_bounds__(512) k_cut() {
    __shared__ int hist[4096];
    __shared__ int wtot[16], wpre[16];
    __shared__ int bres;
    int n = blockIdx.x, tid = threadIdx.x, nt = blockDim.x;
    int lane = tid & 31, w = tid >> 5;
    for (int i = tid; i < 4096; i += nt) hist[i] = 0;
    if (tid == 0) bres = 4095;
    __syncthreads();
    for (int i = tid; i < NSEG; i += nt) {
        unsigned b = __float_as_uint(g_segD[n * NSEGPAD + i]) >> 19;
        atomicAdd(&hist[min(b, 4095u)], 1);
    }
    __syncthreads();
    int s8 = 0;
    #pragma unroll
    for (int j = 0; j < 8; j++) s8 += hist[tid * 8 + j];
    int pre = s8;                       // warp inclusive prefix (ascending)
    #pragma unroll
    for (int o = 1; o < 32; o <<= 1) {
        int t2 = __shfl_up_sync(0xffffffffu, pre, o);
        if (lane >= o) pre += t2;
    }
    if (lane == 31) wtot[w] = pre;
    __syncthreads();
    if (tid < 16) {
        int v = wtot[tid];
        int s = v;
        #pragma unroll
        for (int o = 1; o < 16; o <<= 1) {
            int t2 = __shfl_up_sync(0xffffu, s, o);
            if (tid >= o) s += t2;
        }
        wpre[tid] = s - v;              // exclusive prefix over warps
    }
    __syncthreads();
    int excl = wpre[w] + (pre - s8);    // buckets strictly below tid's chunk
    if (excl < NREF && excl + s8 >= NREF) {
        int cum = excl;
        #pragma unroll
        for (int b = 0; b < 8; b++) {
            cum += hist[tid * 8 + b];
            if (cum >= NREF) { bres = tid * 8 + b; break; }
        }
    }
    __syncthreads();
    int bc = min(bres + 1, 4095);       // +1 bucket: surrogate-vs-exact slop
    if (tid == 0) g_bcut[n] = bc;
    for (int i = tid; i < NSEG; i += nt) {
        unsigned b = __float_as_uint(g_segD[n * NSEGPAD + i]) >> 19;
        if ((int)b <= bc) {
            int pos = atomicAdd(&g_lcnt[n], 1);
            if (pos < LCAP) g_seglist[n][pos] = i;
        }
    }
}

__device__ __forceinline__ void push_cand(int n, float a, float ctr_v, int rnk) {
    float sa = sig_ref(a);
    if (sa > 0.05f) {                           // exact reference gate
        float v = sa * sig_ref(ctr_v);
        if (v > 0.0f) {
            unsigned long long kk =
                ((unsigned long long)__float_as_uint(v) << 32) |
                (0x7FFFFFFFu - (unsigned)rnk);
            int pos = atomicAdd(&g_cnt[n], 1);
            if (pos < CAP) g_cand[n][pos] = kk;
        }
    }
}

__global__ void k_compact(P5 p) {
    int n = blockIdx.y;
    int warp = blockIdx.x * 8 + (threadIdx.x >> 5);
    int lane = threadIdx.x & 31;
    int nwarp = gridDim.x * 8;
    int bcut = g_bcut[n];
    int lcnt = min(g_lcnt[n], LCAP);
    for (int j = warp; j < lcnt; j += nwarp) {
        Seg sg = seg_decode(g_seglist[n][j]);
        const float* lg = p.lg[sg.l] + ((size_t)n * NCLS + sg.c) * sg.HW;
        const float* cd = g_ctrD + n * THWPAD + c_hwb2[sg.l];
        const float* ctp = p.ct[sg.l] + (size_t)n * sg.HW;
        int rb = c_rb[sg.l];
        if (sg.l < 2) {
            int h0 = sg.hw0 + lane * 4;
            int h1 = h0 + 128;
            bool v0 = (h0 + 4 <= sg.HW), v1 = (h1 + 4 <= sg.HW);
            float4 a0, d0, a1, d1;
            if (v0) { a0 = *(const float4*)(lg + h0); d0 = *(const float4*)(cd + h0); }
            if (v1) { a1 = *(const float4*)(lg + h1); d1 = *(const float4*)(cd + h1); }
            if (v0) {
                float aa[4] = {a0.x, a0.y, a0.z, a0.w};
                float dd[4] = {d0.x, d0.y, d0.z, d0.w};
                #pragma unroll
                for (int k = 0; k < 4; k++) {
                    if ((int)(__float_as_uint(Dkey(aa[k], dd[k])) >> 19) <= bcut)
                        push_cand(n, aa[k], ctp[h0 + k], rb + (h0 + k) * NCLS + sg.c);
                }
            }
            if (v1) {
                float aa[4] = {a1.x, a1.y, a1.z, a1.w};
                float dd[4] = {d1.x, d1.y, d1.z, d1.w};
                #pragma unroll
                for (int k = 0; k < 4; k++) {
                    if ((int)(__float_as_uint(Dkey(aa[k], dd[k])) >> 19) <= bcut)
                        push_cand(n, aa[k], ctp[h1 + k], rb + (h1 + k) * NCLS + sg.c);
                }
            }
        } else {
            #pragma unroll
            for (int i = 0; i < 8; i++) {
                int hw = sg.hw0 + lane + i * 32;
                if (hw < sg.HW) {
                    float a = lg[hw];
                    if ((int)(__float_as_uint(Dkey(a, cd[hw])) >> 19) <= bcut)
                        push_cand(n, a, ctp[hw], rb + hw * NCLS + sg.c);
                }
            }
        }
    }
}

__global__ void __launch_bounds__(1024) k_sort(P5 p, float* out) {
    __shared__ union { int hist[8192]; unsigned long long buf[2048]; } u;  // 32KB
    __shared__ int wtot[32], wsuf[32];
    __shared__ int m, bs;
    int n = blockIdx.x, tid = threadIdx.x, nt = blockDim.x;
    int lane = tid & 31, w = tid >> 5;
    int cnt = min(g_cnt[n], CAP);
    for (int i = tid; i < 8192; i += nt) u.hist[i] = 0;
    if (tid == 0) { m = 0; bs = 0; }
    __syncthreads();

    for (int i = tid; i < cnt; i += nt)
        atomicAdd(&u.hist[(int)(g_cand[n][i] >> 51)], 1);
    __syncthreads();

    // hierarchical descending rank-select over 8192 buckets
    int s8 = 0;
    #pragma unroll
    for (int j = 0; j < 8; j++) s8 += u.hist[tid * 8 + j];
    int suf = s8;                        // warp inclusive suffix (toward high lanes)
    #pragma unroll
    for (int o = 1; o < 32; o <<= 1) {
        int t2 = __shfl_down_sync(0xffffffffu, suf, o);
        if (lane + o < 32) suf += t2;
    }
    if (lane == 0) wtot[w] = suf;
    __syncthreads();
    if (tid < 32) {
        int v = wtot[tid];
        int s = v;
        #pragma unroll
        for (int o = 1; o < 32; o <<= 1) {
            int t2 = __shfl_down_sync(0xffffffffu, s, o);
            if (tid + o < 32) s += t2;
        }
        wsuf[tid] = s - v;               // exclusive suffix over warps above
    }
    __syncthreads();
    int above = wsuf[w] + (suf - s8);    // buckets strictly above tid's chunk
    if (above < NREF && above + s8 >= NREF) {
        int cum = above;
        #pragma unroll
        for (int b = 7; b >= 0; b--) {
            cum += u.hist[tid * 8 + b];
            if (cum >= NREF) { bs = tid * 8 + b; break; }
        }
    }
    __syncthreads();
    int bcut2 = bs;
    __syncthreads();                     // hist dead; buf overlay safe

    for (int i = tid; i < cnt; i += nt) {
        unsigned long long kk = g_cand[n][i];
        if ((int)(kk >> 51) >= bcut2) {
            int pos = atomicAdd(&m, 1);
            if (pos < 2048) u.buf[pos] = kk;
        }
    }
    __syncthreads();
    int mm = min(m, 2048);
    for (int i = tid; i < 2048; i += nt) if (i >= mm) u.buf[i] = 0ULL;
    __syncthreads();

    // bitonic sort descending; keys unique (rank embedded) -> deterministic
    for (int k = 2; k <= 2048; k <<= 1) {
        for (int j = k >> 1; j > 0; j >>= 1) {
            for (int i = tid; i < 2048; i += nt) {
                int ixj = i ^ j;
                if (ixj > i) {
                    unsigned long long x = u.buf[i], y = u.buf[ixj];
                    bool desc = ((i & k) == 0);
                    if (desc ? (x < y) : (x > y)) { u.buf[i] = y; u.buf[ixj] = x; }
                }
            }
            __syncthreads();
        }
    }

    if (tid < NREF) {
        unsigned long long kk = u.buf[tid];
        float sc = 0.f, x0 = 0.f, y0 = 0.f, x1 = 0.f, y1 = 0.f;
        int cls = 0, lvl = 0;
        if (kk) {
            float v = __uint_as_float((unsigned)(kk >> 32));
            unsigned rank = 0x7FFFFFFFu - (unsigned)(kk & 0xFFFFFFFFu);
            int l;
            if (rank < 1216000u) l = 0;
            else if (rank < 1520000u) l = 1;
            else if (rank < 1596000u) l = 2;
            else if (rank < 1615760u) l = 3;
            else l = 4;
            int HWl = c_HW[l];
            int r = (int)rank - c_rb[l];
            int loc = r / NCLS;
            cls = r - NCLS * loc;
            lvl = l;
            float strf = c_str[l];
            float px = p.lc[l][2 * loc], py = p.lc[l][2 * loc + 1];
            const float* rg = p.rg[l] + (size_t)n * 4 * HWl;
            float r0 = rg[loc] * strf;
            float r1 = rg[HWl + loc] * strf;
            float r2 = rg[2 * HWl + loc] * strf;
            float r3 = rg[3 * HWl + loc] * strf;
            sc = sqrtf(v);
            x0 = px - r0; y0 = py - r1; x1 = px + r2; y1 = py + r3;
        }
        int o = n * NREF + tid;
        out[o] = sc;
        float* ob = out + NIMG * NREF;
        ob[o * 4 + 0] = x0; ob[o * 4 + 1] = y0;
        ob[o * 4 + 2] = x1; ob[o * 4 + 3] = y1;
        float* oc = out + NIMG * NREF * 5;
        oc[o] = (float)cls;
        float* ol = out + NIMG * NREF * 6;
        ol[o] = (float)lvl;
    }
}

extern "C" void kernel_launch(void* const* d_in, const int* in_sizes, int n_in,
                              void* d_out, int out_size) {
    P5 p;
    for (int l = 0; l < 5; l++) {
        p.lg[l] = (const float*)d_in[4 * l + 0];
        p.rg[l] = (const float*)d_in[4 * l + 1];
        p.ct[l] = (const float*)d_in[4 * l + 2];
        p.lc[l] = (const float*)d_in[4 * l + 3];
    }
    k_ctr<<<(NIMG * THWPAD + 255) / 256, 256>>>(p);
    dim3 g(810, NIMG);       // 810*8 warps >= 6480 segments
    k_minred<<<g, 256>>>(p);
    k_cut<<<NIMG, 512>>>();
    dim3 gc(128, NIMG);      // 1024 warps/image grid-stride over seglist
    k_compact<<<gc, 256>>>(p);
    k_sort<<<NIMG, 1024>>>(p, (float*)d_out);
}